// round 4
// baseline (speedup 1.0000x reference)
#include <cuda_runtime.h>
#include <math.h>
#include <stdint.h>
#include <stdio.h>

#define Nn 8192
#define Dd 768
#define H1s 512
#define H2s 256
#define KK 5

#define BM 64
#define BN 64
#define BKc 16

// ---------------- scratch (device globals; no allocation allowed) ----------
__device__ float g_Y[Nn * Dd];            // X @ W_gm
__device__ float g_XT[Dd * Nn];           // X^T (768 x 8192)
__device__ float g_Ab[67108864];          // S then blended score matrix (N x N)
__device__ float g_L1[Nn * H1s];
__device__ float g_L2[Nn * H2s];
__device__ float g_G[Nn];                 // gating scalar per row
__device__ int   g_top[Nn * KK];
__device__ float g_rowsum[Nn];
__device__ float g_Agg[Nn * Dd];          // (mask.Ab) @ (X*G)
__device__ float g_Xp[Nn * Dd];           // X + Mfeat
__device__ float g_XG[Nn * Dd];           // X * G (rowwise)
__device__ unsigned int g_mask[Nn * 256]; // union adjacency bitmask (8MB)

// ---------------- math helpers ---------------------------------------------
__device__ __forceinline__ float geluf(float x) {
    return 0.5f * x * (1.0f + erff(x * 0.70710678118654752f));
}
__device__ __forceinline__ float softplusf(float x) {
    return fmaxf(x, 0.0f) + log1pf(expf(-fabsf(x)));
}
__device__ __forceinline__ float sigmoidf(float x) {
    return 1.0f / (1.0f + expf(-x));
}

// ---------------- generic NN GEMM body (verified by head-1 path) ------------
// C(M x Nc) = A(M x Kc) @ B(Kc x Nc), row-major.
// EP 0: C = acc
// EP 1: C = gelu(acc + bias[col])
// EP 2: C = resid + gelu(acc * (1/max(rowsum[row],1e-8)) + bias[col])
template <int EP>
__device__ __forceinline__ void gemm_body(
    const float* __restrict__ A, const float* __restrict__ B,
    float* __restrict__ C, int M, int Nc, int Kc,
    const float* __restrict__ bias,
    const float* __restrict__ rowsum,
    const float* __restrict__ resid)
{
    __shared__ float As[BKc][BM + 1];
    __shared__ __align__(16) float Bs[BKc][BN];

    const int bm = blockIdx.y * BM;
    const int bn = blockIdx.x * BN;
    const int tid = threadIdx.x;            // 256 threads
    const int tr = tid >> 4;                 // 0..15
    const int tc = tid & 15;                 // 0..15

    float acc[4][4] = {};

    for (int k0 = 0; k0 < Kc; k0 += BKc) {
        #pragma unroll
        for (int l = 0; l < 4; l++) {
            int idx = tid + l * 256;         // 64x16 A tile
            int m = idx >> 4, k = idx & 15;
            As[k][m] = A[(size_t)(bm + m) * Kc + k0 + k];
        }
        #pragma unroll
        for (int l = 0; l < 4; l++) {
            int idx = tid + l * 256;         // 16x64 B tile
            int k = idx >> 6, n = idx & 63;
            Bs[k][n] = B[(size_t)(k0 + k) * Nc + bn + n];
        }
        __syncthreads();
        #pragma unroll
        for (int k = 0; k < BKc; k++) {
            float4 bv = *reinterpret_cast<const float4*>(&Bs[k][tc * 4]);
            float b[4] = {bv.x, bv.y, bv.z, bv.w};
            float a[4];
            #pragma unroll
            for (int i = 0; i < 4; i++) a[i] = As[k][tr * 4 + i];
            #pragma unroll
            for (int i = 0; i < 4; i++)
                #pragma unroll
                for (int j = 0; j < 4; j++)
                    acc[i][j] += a[i] * b[j];
        }
        __syncthreads();
    }

    #pragma unroll
    for (int i = 0; i < 4; i++) {
        int row = bm + tr * 4 + i;
        float rs = 1.0f;
        if (EP == 2) rs = 1.0f / fmaxf(rowsum[row], 1e-8f);
        float4 o;
        float* po = &o.x;
        #pragma unroll
        for (int j = 0; j < 4; j++) {
            int col = bn + tc * 4 + j;
            float c = acc[i][j];
            if (EP == 2) c *= rs;
            if (EP >= 1) c = geluf(c + bias[col]);
            if (EP == 2) c += resid[(size_t)row * Nc + col];
            po[j] = c;
        }
        *reinterpret_cast<float4*>(&C[(size_t)row * Nc + bn + tc * 4]) = o;
    }
}

__global__ void k_gemm_Y(const float* __restrict__ X, const float* __restrict__ W) {
    gemm_body<0>(X, W, g_Y, Nn, Dd, Dd, nullptr, nullptr, nullptr);
}
__global__ void k_gemm_S() {   // S(raw) = Y @ XT   via the VERIFIED NN GEMM
    gemm_body<0>(g_Y, g_XT, g_Ab, Nn, Nn, Dd, nullptr, nullptr, nullptr);
}
__global__ void k_gemm_L1a(const float* __restrict__ X, const float* __restrict__ w, const float* __restrict__ b) {
    gemm_body<1>(X, w, g_L1, Nn, H1s, Dd, b, nullptr, nullptr);
}
__global__ void k_gemm_L2(const float* __restrict__ w, const float* __restrict__ b) {
    gemm_body<1>(g_L1, w, g_L2, Nn, H2s, H1s, b, nullptr, nullptr);
}
__global__ void k_gemm_gcn(const float* __restrict__ gw, const float* __restrict__ gb, const float* __restrict__ X) {
    gemm_body<2>(g_Agg, gw, g_Xp, Nn, Dd, Dd, gb, g_rowsum, X);
}
__global__ void k_gemm_L1b(const float* __restrict__ w, const float* __restrict__ b) {
    gemm_body<1>(g_Xp, w, g_L1, Nn, H1s, Dd, b, nullptr, nullptr);
}

// ---------------- transpose: XT[k][i] = X[i][k] ------------------------------
__global__ void k_transpose(const float* __restrict__ X)
{
    __shared__ float t[32][33];
    const int bx = blockIdx.x * 32;   // along Dd
    const int by = blockIdx.y * 32;   // along Nn
    #pragma unroll
    for (int dy = 0; dy < 32; dy += 8)
        t[threadIdx.y + dy][threadIdx.x] =
            X[(size_t)(by + threadIdx.y + dy) * Dd + bx + threadIdx.x];
    __syncthreads();
    #pragma unroll
    for (int dy = 0; dy < 32; dy += 8)
        g_XT[(size_t)(bx + threadIdx.y + dy) * Nn + by + threadIdx.x] =
            t[threadIdx.x][threadIdx.y + dy];
}

// ---------------- blend: Ab = al*A + (1-al)*relu(S) --------------------------
__global__ void k_blend(const float* __restrict__ A, const float* __restrict__ ra)
{
    const float al = sigmoidf(*ra);
    const float om = 1.0f - al;
    size_t idx = (size_t)blockIdx.x * blockDim.x + threadIdx.x;
    size_t total = (size_t)Nn * Nn;
    size_t stride = (size_t)gridDim.x * blockDim.x;
    for (size_t p = idx; p < total; p += stride)
        g_Ab[p] = al * A[p] + om * fmaxf(g_Ab[p], 0.0f);
}

// ---------------- per-row top-K, rewritten (register top-5 + merge) ---------
// jax.lax.top_k semantics: k largest, ties -> lowest index.
__global__ void k_topk2()
{
    __shared__ unsigned long long cand[256 * KK];
    __shared__ unsigned long long red[256];

    const int row = blockIdx.x;
    const int tid = threadIdx.x;
    const float* src = &g_Ab[(size_t)row * Nn];

    unsigned long long loc[KK];
    #pragma unroll
    for (int t = 0; t < KK; t++) loc[t] = 0ULL;

    for (int j = tid; j < Nn; j += 256) {
        unsigned int u = __float_as_uint(src[j]);
        u ^= (u >> 31) ? 0xFFFFFFFFu : 0x80000000u;   // order-preserving map
        unsigned long long key =
            ((unsigned long long)u << 32) | (unsigned long long)(0xFFFFFFFFu - (unsigned)j);
        if (key > loc[KK - 1]) {
            loc[KK - 1] = key;
            #pragma unroll
            for (int t = KK - 1; t > 0; t--) {
                if (loc[t] > loc[t - 1]) {
                    unsigned long long tmp = loc[t]; loc[t] = loc[t - 1]; loc[t - 1] = tmp;
                }
            }
        }
    }
    #pragma unroll
    for (int t = 0; t < KK; t++) cand[tid * KK + t] = loc[t];
    __syncthreads();

    for (int t = 0; t < KK; t++) {
        unsigned long long m = 0ULL;
        for (int p = tid; p < 256 * KK; p += 256)
            if (cand[p] > m) m = cand[p];
        red[tid] = m;
        __syncthreads();
        for (int s = 128; s > 0; s >>= 1) {
            if (tid < s && red[tid + s] > red[tid]) red[tid] = red[tid + s];
            __syncthreads();
        }
        unsigned long long best = red[0];
        if (tid == 0)
            g_top[row * KK + t] = (int)(0xFFFFFFFFu - (unsigned)(best & 0xFFFFFFFFULL));
        for (int p = tid; p < 256 * KK; p += 256)
            if (cand[p] == best) cand[p] = 0ULL;   // keys unique (index embedded)
        __syncthreads();
    }
}

// ---------------- head tail: r = L2@wh + bh -> (m, v, a, b) [+ gate G] ------
__global__ void k_head_tail(const float* __restrict__ wh, const float* __restrict__ bh,
                            float* __restrict__ out, int computeG,
                            const float* __restrict__ gam)
{
    __shared__ float swh[4 * H2s];   // transposed: swh[c*256 + d]
    for (int i = threadIdx.x; i < 4 * H2s; i += blockDim.x) {
        int c = i >> 8, d = i & 255;
        swh[i] = wh[d * 4 + c];
    }
    __syncthreads();

    const int warp = threadIdx.x >> 5;
    const int lane = threadIdx.x & 31;
    const int row = blockIdx.x * 8 + warp;

    float a0 = 0.f, a1 = 0.f, a2 = 0.f, a3 = 0.f;
    for (int d = lane; d < H2s; d += 32) {
        float v = g_L2[(size_t)row * H2s + d];
        a0 += v * swh[0 * H2s + d];
        a1 += v * swh[1 * H2s + d];
        a2 += v * swh[2 * H2s + d];
        a3 += v * swh[3 * H2s + d];
    }
    #pragma unroll
    for (int off = 16; off > 0; off >>= 1) {
        a0 += __shfl_xor_sync(0xffffffffu, a0, off);
        a1 += __shfl_xor_sync(0xffffffffu, a1, off);
        a2 += __shfl_xor_sync(0xffffffffu, a2, off);
        a3 += __shfl_xor_sync(0xffffffffu, a3, off);
    }
    if (lane == 0) {
        float r0 = a0 + bh[0], r1 = a1 + bh[1], r2 = a2 + bh[2], r3 = a3 + bh[3];
        float m  = r0;
        float vv = softplusf(r1) + 1e-6f;
        float aa = softplusf(r2) + 1.0f + 1e-6f;
        float bb = softplusf(r3) + 1e-6f;
        out[row]          = m;
        out[Nn + row]     = vv;
        out[2 * Nn + row] = aa;
        out[3 * Nn + row] = bb;
        if (computeG) {
            float u0 = bb / fmaxf(aa - 1.0f, 1e-8f);
            g_G[row] = 1.0f - (*gam) * sigmoidf(u0);
        }
    }
}

// ---------------- mask construction (dense, literal) ------------------------
__global__ void k_zero_mask()
{
    size_t idx = (size_t)blockIdx.x * blockDim.x + threadIdx.x;
    size_t total = (size_t)Nn * 256;
    size_t stride = (size_t)gridDim.x * blockDim.x;
    for (size_t p = idx; p < total; p += stride) g_mask[p] = 0u;
}

__global__ void k_set_mask()
{
    int e = blockIdx.x * blockDim.x + threadIdx.x;
    if (e >= Nn * KK) return;
    int i = e / KK;
    int j = g_top[e];
    if (j == i) return;   // diagonal removed after masking in reference
    atomicOr(&g_mask[i * 256 + (j >> 5)], 1u << (j & 31));
    atomicOr(&g_mask[j * 256 + (i >> 5)], 1u << (i & 31));
}

// ---------------- XG = X * G (rowwise) --------------------------------------
__global__ void k_xg(const float* __restrict__ X)
{
    size_t idx = (size_t)blockIdx.x * blockDim.x + threadIdx.x;
    size_t total = (size_t)Nn * Dd;
    size_t stride = (size_t)gridDim.x * blockDim.x;
    for (size_t p = idx; p < total; p += stride) {
        int row = (int)(p / Dd);
        g_XG[p] = X[p] * g_G[row];
    }
}

// ---------------- dense rowsum of masked Ab ----------------------------------
__global__ void k_rowsum()
{
    __shared__ float red[256];
    const int row = blockIdx.x;
    const float* src = &g_Ab[(size_t)row * Nn];
    const unsigned int* mrow = &g_mask[row * 256];

    float s = 0.0f;
    for (int j = threadIdx.x; j < Nn; j += 256) {
        unsigned int w = mrow[j >> 5];
        if (w & (1u << (j & 31))) s += src[j];
    }
    red[threadIdx.x] = s;
    __syncthreads();
    for (int st = 128; st > 0; st >>= 1) {
        if (threadIdx.x < st) red[threadIdx.x] += red[threadIdx.x + st];
        __syncthreads();
    }
    if (threadIdx.x == 0) g_rowsum[row] = red[0];
}

// ---------------- dense masked SpMM: Agg = (mask .* Ab) @ XG -----------------
__global__ void k_spmm()
{
    __shared__ float As[BKc][BM + 1];
    __shared__ __align__(16) float Bs[BKc][BN];

    const int bm = blockIdx.y * BM;
    const int bn = blockIdx.x * BN;
    const int tid = threadIdx.x;
    const int tr = tid >> 4;
    const int tc = tid & 15;

    float acc[4][4] = {};

    for (int k0 = 0; k0 < Nn; k0 += BKc) {
        #pragma unroll
        for (int l = 0; l < 4; l++) {
            int idx = tid + l * 256;
            int m = idx >> 4, k = idx & 15;
            int row = bm + m, col = k0 + k;
            unsigned int w = g_mask[row * 256 + (col >> 5)];
            float v = 0.0f;
            if (w & (1u << (col & 31))) v = g_Ab[(size_t)row * Nn + col];
            As[k][m] = v;
        }
        #pragma unroll
        for (int l = 0; l < 4; l++) {
            int idx = tid + l * 256;
            int k = idx >> 6, n = idx & 63;
            Bs[k][n] = g_XG[(size_t)(k0 + k) * Dd + bn + n];
        }
        __syncthreads();
        #pragma unroll
        for (int k = 0; k < BKc; k++) {
            float4 bv = *reinterpret_cast<const float4*>(&Bs[k][tc * 4]);
            float b[4] = {bv.x, bv.y, bv.z, bv.w};
            float a[4];
            #pragma unroll
            for (int i = 0; i < 4; i++) a[i] = As[k][tr * 4 + i];
            #pragma unroll
            for (int i = 0; i < 4; i++)
                #pragma unroll
                for (int j = 0; j < 4; j++)
                    acc[i][j] += a[i] * b[j];
        }
        __syncthreads();
    }

    #pragma unroll
    for (int i = 0; i < 4; i++) {
        int row = bm + tr * 4 + i;
        float4 o = {acc[i][0], acc[i][1], acc[i][2], acc[i][3]};
        *reinterpret_cast<float4*>(&g_Agg[(size_t)row * Dd + bn + tc * 4]) = o;
    }
}

// ---------------- launch ----------------------------------------------------
extern "C" void kernel_launch(void* const* d_in, const int* in_sizes, int n_in,
                              void* d_out, int out_size)
{
    // diagnostic: reveal true input ordering in the error log if we fail
    fprintf(stderr, "[diag] n_in=%d out=%d sizes:", n_in, out_size);
    for (int i = 0; i < n_in; i++) fprintf(stderr, " %d", in_sizes[i]);
    fprintf(stderr, "\n");

    const float* X     = (const float*)d_in[0];
    const float* A     = (const float*)d_in[1];
    const float* W_gm  = (const float*)d_in[2];
    const float* ra    = (const float*)d_in[3];
    const float* gam   = (const float*)d_in[4];
    const float* ih_w1 = (const float*)d_in[5];
    const float* ih_b1 = (const float*)d_in[6];
    const float* ih_w2 = (const float*)d_in[7];
    const float* ih_b2 = (const float*)d_in[8];
    const float* ih_wh = (const float*)d_in[9];
    const float* ih_bh = (const float*)d_in[10];
    const float* gcn_w = (const float*)d_in[11];
    const float* gcn_b = (const float*)d_in[12];
    const float* fh_w1 = (const float*)d_in[13];
    const float* fh_b1 = (const float*)d_in[14];
    const float* fh_w2 = (const float*)d_in[15];
    const float* fh_b2 = (const float*)d_in[16];
    const float* fh_wh = (const float*)d_in[17];
    const float* fh_bh = (const float*)d_in[18];
    float* out = (float*)d_out;

    dim3 blk(256);

    // 1. Y = X @ W_gm ; XT = X^T
    k_gemm_Y<<<dim3(Dd / BN, Nn / BM), blk>>>(X, W_gm);
    k_transpose<<<dim3(Dd / 32, Nn / 32), dim3(32, 8)>>>(X);

    // 2. S = Y @ XT (verified GEMM path), then blend into Ab
    k_gemm_S<<<dim3(Nn / BN, Nn / BM), blk>>>();
    k_blend<<<32768, blk>>>(A, ra);

    // 3. per-row top-5 (rewritten)
    k_topk2<<<Nn, blk>>>();

    // 4. union mask
    k_zero_mask<<<2048, blk>>>();
    k_set_mask<<<(Nn * KK + 255) / 256, blk>>>();

    // 5. NIG head 1 on X -> out[0..4N) and gate G
    k_gemm_L1a<<<dim3(H1s / BN, Nn / BM), blk>>>(X, ih_w1, ih_b1);
    k_gemm_L2<<<dim3(H2s / BN, Nn / BM), blk>>>(ih_w2, ih_b2);
    k_head_tail<<<Nn / 8, blk>>>(ih_wh, ih_bh, out, 1, gam);

    // 6. XG = X * G, rowsum = (mask.*Ab).sum(-1), Agg = (mask.*Ab) @ XG
    k_xg<<<4096, blk>>>(X);
    k_rowsum<<<Nn, blk>>>();
    k_spmm<<<dim3(Dd / BN, Nn / BM), blk>>>();

    // 7. Xp = X + gelu((Agg / rowsum) @ gcn_w + gcn_b)
    k_gemm_gcn<<<dim3(Dd / BN, Nn / BM), blk>>>(gcn_w, gcn_b, X);

    // 8. NIG head 2 on Xp -> out[4N..8N)
    k_gemm_L1b<<<dim3(H1s / BN, Nn / BM), blk>>>(fh_w1, fh_b1);
    k_gemm_L2<<<dim3(H2s / BN, Nn / BM), blk>>>(fh_w2, fh_b2);
    k_head_tail<<<Nn / 8, blk>>>(fh_wh, fh_bh, out + 4 * Nn, 0, nullptr);
}

// round 5
// speedup vs baseline: 2.7056x; 2.7056x over previous
#include <cuda_runtime.h>
#include <math.h>
#include <stdint.h>

#define Nn 8192
#define Dd 768
#define H1s 512
#define H2s 256
#define KK 5

typedef unsigned long long ull;

// ---------------- scratch (device globals; no allocation allowed) ----------
__device__ float g_Y[Nn * Dd];            // X @ W_gm
__device__ float g_XT[Dd * Nn];           // X^T (768 x 8192)
__device__ float g_Ab[67108864];          // blended score matrix (N x N)
__device__ float g_L1[Nn * H1s];
__device__ float g_L2[Nn * H2s];
__device__ float g_G[Nn];                 // gating scalar per row
__device__ int   g_top[Nn * KK];
__device__ float g_rowsum[Nn];
__device__ float g_Agg[Nn * Dd];          // sum_j Ag[i,j]*G[j]*X[j]
__device__ float g_Xp[Nn * Dd];           // X + Mfeat
__device__ unsigned int g_mask[Nn * 256]; // union adjacency bitmask (8MB)

// ---------------- math helpers ---------------------------------------------
__device__ __forceinline__ float geluf(float x) {
    return 0.5f * x * (1.0f + erff(x * 0.70710678118654752f));
}
__device__ __forceinline__ float softplusf(float x) {
    return fmaxf(x, 0.0f) + log1pf(expf(-fabsf(x)));
}
__device__ __forceinline__ float sigmoidf(float x) {
    return 1.0f / (1.0f + expf(-x));
}

// ---------------- packed f32x2 helpers (Blackwell FFMA2 path) ---------------
__device__ __forceinline__ ull pack2(float lo, float hi) {
    ull r; asm("mov.b64 %0, {%1, %2};" : "=l"(r) : "f"(lo), "f"(hi)); return r;
}
__device__ __forceinline__ void unpack2(ull v, float& lo, float& hi) {
    asm("mov.b64 {%0, %1}, %2;" : "=f"(lo), "=f"(hi) : "l"(v));
}
__device__ __forceinline__ void fma2(ull& d, ull a, ull b) {
    asm("fma.rn.f32x2 %0, %1, %2, %0;" : "+l"(d) : "l"(a), "l"(b));
}

// ---------------- 128x128x16 double-buffered f32x2 GEMM ---------------------
// C(M x Nc) = A(M x Kc) @ B(Kc x Nc), row-major. M,Nc mult of 128, Kc mult 16.
// EP 0: C = acc
// EP 1: C = gelu(acc + bias[col])
// EP 2: C = resid + gelu(acc * (1/max(rowsum[row],1e-8)) + bias[col])
// EP 3: C = al*Aecfp + (1-al)*relu(acc)           (al = sigmoid(*ra))
template <int EP>
__global__ void __launch_bounds__(256, 2) k_gemm128(
    const float* __restrict__ A, const float* __restrict__ B,
    float* __restrict__ C, int Nc, int Kc,
    const float* __restrict__ bias,
    const float* __restrict__ rowsum,
    const float* __restrict__ resid,
    const float* __restrict__ Aecfp,
    const float* __restrict__ ra)
{
    __shared__ float As[2][16][128];
    __shared__ float Bs[2][16][128];

    const int bm = blockIdx.y * 128;
    const int bn = blockIdx.x * 128;
    const int tid = threadIdx.x;           // 256 threads
    const int tr = tid >> 4;               // 0..15
    const int tc = tid & 15;               // 0..15

    float al = 0.0f, om = 0.0f;
    if (EP == 3) { al = sigmoidf(*ra); om = __fsub_rn(1.0f, al); }

    ull acc2[8][4];
    #pragma unroll
    for (int i = 0; i < 8; i++)
        #pragma unroll
        for (int j = 0; j < 4; j++) acc2[i][j] = 0ULL;

    float4 pa[2], pb[2];

    auto loadG = [&](int k0) {
        #pragma unroll
        for (int l = 0; l < 2; l++) {
            int idx = tid + l * 256;               // A: 512 float4 (128 x 16)
            int m = idx >> 2, kq = idx & 3;
            pa[l] = *reinterpret_cast<const float4*>(
                &A[(size_t)(bm + m) * Kc + k0 + kq * 4]);
        }
        #pragma unroll
        for (int l = 0; l < 2; l++) {
            int idx = tid + l * 256;               // B: 512 float4 (16 x 128)
            int k = idx >> 5, nq = idx & 31;
            pb[l] = *reinterpret_cast<const float4*>(
                &B[(size_t)(k0 + k) * Nc + bn + nq * 4]);
        }
    };
    auto storeS = [&](int buf) {
        #pragma unroll
        for (int l = 0; l < 2; l++) {
            int idx = tid + l * 256;
            int m = idx >> 2, kq = idx & 3;
            As[buf][kq * 4 + 0][m] = pa[l].x;
            As[buf][kq * 4 + 1][m] = pa[l].y;
            As[buf][kq * 4 + 2][m] = pa[l].z;
            As[buf][kq * 4 + 3][m] = pa[l].w;
        }
        #pragma unroll
        for (int l = 0; l < 2; l++) {
            int idx = tid + l * 256;
            int k = idx >> 5, nq = idx & 31;
            *reinterpret_cast<float4*>(&Bs[buf][k][nq * 4]) = pb[l];
        }
    };
    auto compute = [&](int buf) {
        #pragma unroll
        for (int k = 0; k < 16; k++) {
            float4 a0 = *reinterpret_cast<const float4*>(&As[buf][k][tr * 4]);
            float4 a1 = *reinterpret_cast<const float4*>(&As[buf][k][64 + tr * 4]);
            float4 b0 = *reinterpret_cast<const float4*>(&Bs[buf][k][tc * 4]);
            float4 b1 = *reinterpret_cast<const float4*>(&Bs[buf][k][64 + tc * 4]);
            ull bp[4] = {pack2(b0.x, b0.y), pack2(b0.z, b0.w),
                         pack2(b1.x, b1.y), pack2(b1.z, b1.w)};
            float av[8] = {a0.x, a0.y, a0.z, a0.w, a1.x, a1.y, a1.z, a1.w};
            #pragma unroll
            for (int i = 0; i < 8; i++) {
                ull ap = pack2(av[i], av[i]);
                #pragma unroll
                for (int j = 0; j < 4; j++) fma2(acc2[i][j], ap, bp[j]);
            }
        }
    };

    loadG(0);
    storeS(0);
    __syncthreads();
    int buf = 0;
    for (int k0 = 16; k0 < Kc; k0 += 16) {
        loadG(k0);
        compute(buf);
        storeS(1 - buf);
        __syncthreads();
        buf ^= 1;
    }
    compute(buf);

    #pragma unroll
    for (int i = 0; i < 8; i++) {
        int row = bm + ((i < 4) ? (tr * 4 + i) : (64 + tr * 4 + (i - 4)));
        float c[8];
        unpack2(acc2[i][0], c[0], c[1]);
        unpack2(acc2[i][1], c[2], c[3]);
        unpack2(acc2[i][2], c[4], c[5]);
        unpack2(acc2[i][3], c[6], c[7]);

        float rs = 1.0f;
        if (EP == 2) rs = 1.0f / fmaxf(rowsum[row], 1e-8f);

        #pragma unroll
        for (int g = 0; g < 2; g++) {
            int col0 = bn + g * 64 + tc * 4;
            size_t base = (size_t)row * Nc + col0;
            float4 o;
            float* po = &o.x;
            if (EP == 3) {
                float4 av = *reinterpret_cast<const float4*>(&Aecfp[base]);
                const float* pav = &av.x;
                #pragma unroll
                for (int j = 0; j < 4; j++)
                    po[j] = __fadd_rn(__fmul_rn(al, pav[j]),
                                      __fmul_rn(om, fmaxf(c[g * 4 + j], 0.0f)));
            } else {
                #pragma unroll
                for (int j = 0; j < 4; j++) {
                    float v = c[g * 4 + j];
                    if (EP == 2) v *= rs;
                    if (EP == 1 || EP == 2) v = geluf(v + bias[col0 + j]);
                    if (EP == 2) v += resid[base + j];
                    po[j] = v;
                }
            }
            *reinterpret_cast<float4*>(&C[base]) = o;
        }
    }
}

// ---------------- transpose: XT[k][i] = X[i][k] ------------------------------
__global__ void k_transpose(const float* __restrict__ X)
{
    __shared__ float t[32][33];
    const int bx = blockIdx.x * 32;   // along Dd
    const int by = blockIdx.y * 32;   // along Nn
    #pragma unroll
    for (int dy = 0; dy < 32; dy += 8)
        t[threadIdx.y + dy][threadIdx.x] =
            X[(size_t)(by + threadIdx.y + dy) * Dd + bx + threadIdx.x];
    __syncthreads();
    #pragma unroll
    for (int dy = 0; dy < 32; dy += 8)
        g_XT[(size_t)(bx + threadIdx.y + dy) * Nn + by + threadIdx.x] =
            t[threadIdx.x][threadIdx.y + dy];
}

// ---------------- per-row top-K (register top-5 + merge; VERIFIED R4) -------
__global__ void k_topk2()
{
    __shared__ unsigned long long cand[256 * KK];
    __shared__ unsigned long long red[256];

    const int row = blockIdx.x;
    const int tid = threadIdx.x;
    const float* src = &g_Ab[(size_t)row * Nn];

    unsigned long long loc[KK];
    #pragma unroll
    for (int t = 0; t < KK; t++) loc[t] = 0ULL;

    for (int j = tid; j < Nn; j += 256) {
        unsigned int u = __float_as_uint(src[j]);
        u ^= (u >> 31) ? 0xFFFFFFFFu : 0x80000000u;   // order-preserving map
        unsigned long long key =
            ((unsigned long long)u << 32) | (unsigned long long)(0xFFFFFFFFu - (unsigned)j);
        if (key > loc[KK - 1]) {
            loc[KK - 1] = key;
            #pragma unroll
            for (int t = KK - 1; t > 0; t--) {
                if (loc[t] > loc[t - 1]) {
                    unsigned long long tmp = loc[t]; loc[t] = loc[t - 1]; loc[t - 1] = tmp;
                }
            }
        }
    }
    #pragma unroll
    for (int t = 0; t < KK; t++) cand[tid * KK + t] = loc[t];
    __syncthreads();

    for (int t = 0; t < KK; t++) {
        unsigned long long m = 0ULL;
        for (int p = tid; p < 256 * KK; p += 256)
            if (cand[p] > m) m = cand[p];
        red[tid] = m;
        __syncthreads();
        for (int s = 128; s > 0; s >>= 1) {
            if (tid < s && red[tid + s] > red[tid]) red[tid] = red[tid + s];
            __syncthreads();
        }
        unsigned long long best = red[0];
        if (tid == 0)
            g_top[row * KK + t] = (int)(0xFFFFFFFFu - (unsigned)(best & 0xFFFFFFFFULL));
        for (int p = tid; p < 256 * KK; p += 256)
            if (cand[p] == best) cand[p] = 0ULL;
        __syncthreads();
    }
}

// ---------------- head tail ---------------------------------------------------
__global__ void k_head_tail(const float* __restrict__ wh, const float* __restrict__ bh,
                            float* __restrict__ out, int computeG,
                            const float* __restrict__ gam)
{
    __shared__ float swh[4 * H2s];
    for (int i = threadIdx.x; i < 4 * H2s; i += blockDim.x) {
        int c = i >> 8, d = i & 255;
        swh[i] = wh[d * 4 + c];
    }
    __syncthreads();

    const int warp = threadIdx.x >> 5;
    const int lane = threadIdx.x & 31;
    const int row = blockIdx.x * 8 + warp;

    float a0 = 0.f, a1 = 0.f, a2 = 0.f, a3 = 0.f;
    for (int d = lane; d < H2s; d += 32) {
        float v = g_L2[(size_t)row * H2s + d];
        a0 += v * swh[0 * H2s + d];
        a1 += v * swh[1 * H2s + d];
        a2 += v * swh[2 * H2s + d];
        a3 += v * swh[3 * H2s + d];
    }
    #pragma unroll
    for (int off = 16; off > 0; off >>= 1) {
        a0 += __shfl_xor_sync(0xffffffffu, a0, off);
        a1 += __shfl_xor_sync(0xffffffffu, a1, off);
        a2 += __shfl_xor_sync(0xffffffffu, a2, off);
        a3 += __shfl_xor_sync(0xffffffffu, a3, off);
    }
    if (lane == 0) {
        float r0 = a0 + bh[0], r1 = a1 + bh[1], r2 = a2 + bh[2], r3 = a3 + bh[3];
        float m  = r0;
        float vv = softplusf(r1) + 1e-6f;
        float aa = softplusf(r2) + 1.0f + 1e-6f;
        float bb = softplusf(r3) + 1e-6f;
        out[row]          = m;
        out[Nn + row]     = vv;
        out[2 * Nn + row] = aa;
        out[3 * Nn + row] = bb;
        if (computeG) {
            float u0 = bb / fmaxf(aa - 1.0f, 1e-8f);
            g_G[row] = 1.0f - (*gam) * sigmoidf(u0);
        }
    }
}

// ---------------- mask construction ------------------------------------------
__global__ void k_zero_mask()
{
    size_t idx = (size_t)blockIdx.x * blockDim.x + threadIdx.x;
    size_t total = (size_t)Nn * 256;
    size_t stride = (size_t)gridDim.x * blockDim.x;
    for (size_t p = idx; p < total; p += stride) g_mask[p] = 0u;
}

__global__ void k_set_mask()
{
    int e = blockIdx.x * blockDim.x + threadIdx.x;
    if (e >= Nn * KK) return;
    int i = e / KK;
    int j = g_top[e];
    if (j == i) return;
    atomicOr(&g_mask[i * 256 + (j >> 5)], 1u << (j & 31));
    atomicOr(&g_mask[j * 256 + (i >> 5)], 1u << (i & 31));
}

// ---------------- sparse per-row aggregation (deterministic, no atomics) ----
#define EB 2048
__global__ void k_edges(const float* __restrict__ X)
{
    __shared__ unsigned int mwords[256];
    __shared__ int sc[256];
    __shared__ int lst[EB];
    __shared__ float cf[EB];
    __shared__ float abv[EB];
    __shared__ float s_rowsum;

    const int row = blockIdx.x;
    const int tid = threadIdx.x;

    unsigned int w0 = g_mask[row * 256 + tid];
    mwords[tid] = w0;
    int myp = __popc(w0);
    sc[tid] = myp;
    __syncthreads();
    for (int off = 1; off < 256; off <<= 1) {
        int v = (tid >= off) ? sc[tid - off] : 0;
        __syncthreads();
        sc[tid] += v;
        __syncthreads();
    }
    const int myoff = sc[tid] - myp;
    const int E = sc[255];
    if (tid == 0) s_rowsum = 0.0f;
    __syncthreads();

    float racc0 = 0.f, racc1 = 0.f, racc2 = 0.f;

    for (int start = 0; start < E; start += EB) {
        int end = (E < start + EB) ? E : (start + EB);
        int cnt = end - start;
        {
            unsigned int w = mwords[tid];
            int pos = myoff;
            while (w) {
                int b = __ffs(w) - 1;
                w &= w - 1;
                if (pos >= start && pos < end) lst[pos - start] = tid * 32 + b;
                pos++;
            }
        }
        __syncthreads();
        for (int e = tid; e < cnt; e += 256) {
            int j = lst[e];
            float ab = g_Ab[(size_t)row * Nn + j];
            abv[e] = ab;
            cf[e] = ab * g_G[j];
        }
        __syncthreads();
        if (tid == 0) {
            float s = s_rowsum;
            for (int e = 0; e < cnt; e++) s += abv[e];
            s_rowsum = s;
        }
        for (int e = 0; e < cnt; e++) {
            float c = cf[e];
            const float* xr = &X[(size_t)lst[e] * Dd];
            racc0 += c * xr[tid];
            racc1 += c * xr[tid + 256];
            racc2 += c * xr[tid + 512];
        }
        __syncthreads();
    }

    g_Agg[(size_t)row * Dd + tid]       = racc0;
    g_Agg[(size_t)row * Dd + tid + 256] = racc1;
    g_Agg[(size_t)row * Dd + tid + 512] = racc2;
    if (tid == 0) g_rowsum[row] = s_rowsum;
}

// ---------------- launch ----------------------------------------------------
extern "C" void kernel_launch(void* const* d_in, const int* in_sizes, int n_in,
                              void* d_out, int out_size)
{
    const float* X     = (const float*)d_in[0];
    const float* A     = (const float*)d_in[1];
    const float* W_gm  = (const float*)d_in[2];
    const float* ra    = (const float*)d_in[3];
    const float* gam   = (const float*)d_in[4];
    const float* ih_w1 = (const float*)d_in[5];
    const float* ih_b1 = (const float*)d_in[6];
    const float* ih_w2 = (const float*)d_in[7];
    const float* ih_b2 = (const float*)d_in[8];
    const float* ih_wh = (const float*)d_in[9];
    const float* ih_bh = (const float*)d_in[10];
    const float* gcn_w = (const float*)d_in[11];
    const float* gcn_b = (const float*)d_in[12];
    const float* fh_w1 = (const float*)d_in[13];
    const float* fh_b1 = (const float*)d_in[14];
    const float* fh_w2 = (const float*)d_in[15];
    const float* fh_b2 = (const float*)d_in[16];
    const float* fh_wh = (const float*)d_in[17];
    const float* fh_bh = (const float*)d_in[18];
    float* out = (float*)d_out;

    // Resolve device-global scratch addresses (no allocation; pure query)
    static float *pY = nullptr, *pXT = nullptr, *pAb = nullptr, *pL1 = nullptr,
                 *pL2 = nullptr, *pAgg = nullptr, *pXp = nullptr, *pRs = nullptr;
    if (!pY) {
        cudaGetSymbolAddress((void**)&pY,  g_Y);
        cudaGetSymbolAddress((void**)&pXT, g_XT);
        cudaGetSymbolAddress((void**)&pAb, g_Ab);
        cudaGetSymbolAddress((void**)&pL1, g_L1);
        cudaGetSymbolAddress((void**)&pL2, g_L2);
        cudaGetSymbolAddress((void**)&pAgg, g_Agg);
        cudaGetSymbolAddress((void**)&pXp, g_Xp);
        cudaGetSymbolAddress((void**)&pRs, g_rowsum);
    }

    dim3 blk(256);

    // 1. Y = X @ W_gm ; XT = X^T
    k_gemm128<0><<<dim3(Dd / 128, Nn / 128), blk>>>(
        X, W_gm, pY, Dd, Dd, nullptr, nullptr, nullptr, nullptr, nullptr);
    k_transpose<<<dim3(Dd / 32, Nn / 32), dim3(32, 8)>>>(X);

    // 2. Ab = al*A + (1-al)*relu(Y @ XT)   (fused blend epilogue)
    k_gemm128<3><<<dim3(Nn / 128, Nn / 128), blk>>>(
        pY, pXT, pAb, Nn, Dd, nullptr, nullptr, nullptr, A, ra);

    // 3. per-row top-5
    k_topk2<<<Nn, blk>>>();

    // 4. union mask
    k_zero_mask<<<2048, blk>>>();
    k_set_mask<<<(Nn * KK + 255) / 256, blk>>>();

    // 5. NIG head 1 on X -> out[0..4N) and gate G
    k_gemm128<1><<<dim3(H1s / 128, Nn / 128), blk>>>(
        X, ih_w1, pL1, H1s, Dd, ih_b1, nullptr, nullptr, nullptr, nullptr);
    k_gemm128<1><<<dim3(H2s / 128, Nn / 128), blk>>>(
        pL1, ih_w2, pL2, H2s, H1s, ih_b2, nullptr, nullptr, nullptr, nullptr);
    k_head_tail<<<Nn / 8, blk>>>(ih_wh, ih_bh, out, 1, gam);

    // 6. sparse aggregation: Agg, rowsum
    k_edges<<<Nn, blk>>>(X);

    // 7. Xp = X + gelu((Agg / rowsum) @ gcn_w + gcn_b)
    k_gemm128<2><<<dim3(Dd / 128, Nn / 128), blk>>>(
        pAgg, gcn_w, pXp, Dd, Dd, gcn_b, pRs, X, nullptr, nullptr);

    // 8. NIG head 2 on Xp -> out[4N..8N)
    k_gemm128<1><<<dim3(H1s / 128, Nn / 128), blk>>>(
        pXp, fh_w1, pL1, H1s, Dd, fh_b1, nullptr, nullptr, nullptr, nullptr);
    k_gemm128<1><<<dim3(H2s / 128, Nn / 128), blk>>>(
        pL1, fh_w2, pL2, H2s, H1s, fh_b2, nullptr, nullptr, nullptr, nullptr);
    k_head_tail<<<Nn / 8, blk>>>(fh_wh, fh_bh, out + 4 * Nn, 0, nullptr);
}

// round 7
// speedup vs baseline: 3.2794x; 1.2121x over previous
#include <cuda_runtime.h>
#include <cuda_bf16.h>
#include <math.h>
#include <stdint.h>

#define Nn 8192
#define Dd 768
#define H1s 512
#define H2s 256
#define KK 5

typedef unsigned long long ull;

// ---------------- scratch (device globals; no allocation allowed) ----------
__device__ float g_Y[Nn * Dd];              // X @ W_gm
__device__ float g_Ab[67108864];            // blended score matrix (N x N)
__device__ float g_L1[Nn * H1s];
__device__ float g_L2[Nn * H2s];
__device__ float g_G[Nn];                   // gating scalar per row
__device__ int   g_top[Nn * KK];
__device__ float g_rowsum[Nn];
__device__ float g_Agg[Nn * Dd];            // sum_j Ag[i,j]*G[j]*X[j]
__device__ float g_Xp[Nn * Dd];             // X + Mfeat
__device__ unsigned int g_mask[Nn * 256];   // union adjacency bitmask (8MB)
__device__ __nv_bfloat16 g_Yh[Nn * Dd];     // bf16 split of Y (hi)
__device__ __nv_bfloat16 g_Yl[Nn * Dd];     // bf16 split of Y (lo)
__device__ __nv_bfloat16 g_Xh[Nn * Dd];     // bf16 split of X (hi)
__device__ __nv_bfloat16 g_Xl[Nn * Dd];     // bf16 split of X (lo)

// ---------------- math helpers ---------------------------------------------
__device__ __forceinline__ float geluf(float x) {
    return 0.5f * x * (1.0f + erff(x * 0.70710678118654752f));
}
__device__ __forceinline__ float softplusf(float x) {
    return fmaxf(x, 0.0f) + log1pf(expf(-fabsf(x)));
}
__device__ __forceinline__ float sigmoidf(float x) {
    return 1.0f / (1.0f + expf(-x));
}

// ---------------- packed f32x2 helpers ---------------------------------------
__device__ __forceinline__ ull pack2(float lo, float hi) {
    ull r; asm("mov.b64 %0, {%1, %2};" : "=l"(r) : "f"(lo), "f"(hi)); return r;
}
__device__ __forceinline__ void unpack2(ull v, float& lo, float& hi) {
    asm("mov.b64 {%0, %1}, %2;" : "=f"(lo), "=f"(hi) : "l"(v));
}
__device__ __forceinline__ void fma2(ull& d, ull a, ull b) {
    asm("fma.rn.f32x2 %0, %1, %2, %0;" : "+l"(d) : "l"(a), "l"(b));
}

// ---------------- HMMA m16n8k16 bf16 wrapper (sm_80+, no 'a' arch needed) ---
__device__ __forceinline__ void mma16816(float* d, const uint32_t* a, const uint32_t* b) {
    asm volatile(
        "mma.sync.aligned.m16n8k16.row.col.f32.bf16.bf16.f32 "
        "{%0,%1,%2,%3}, {%4,%5,%6,%7}, {%8,%9}, {%0,%1,%2,%3};"
        : "+f"(d[0]), "+f"(d[1]), "+f"(d[2]), "+f"(d[3])
        : "r"(a[0]), "r"(a[1]), "r"(a[2]), "r"(a[3]), "r"(b[0]), "r"(b[1]));
}

__device__ __forceinline__ uint32_t smem_to_u32(const void* p) {
    uint32_t a;
    asm("{ .reg .u64 t; cvta.to.shared.u64 t, %1; cvt.u32.u64 %0, t; }"
        : "=r"(a) : "l"(p));
    return a;
}
__device__ __forceinline__ void cp_async16(uint32_t dst, const void* src) {
    asm volatile("cp.async.cg.shared.global [%0], [%1], 16;"
                 :: "r"(dst), "l"(src) : "memory");
}
#define CP_COMMIT() asm volatile("cp.async.commit_group;" ::: "memory")
#define CP_WAIT(n)  asm volatile("cp.async.wait_group %0;" :: "n"(n) : "memory")

// ---------------- bf16 split: hi = bf16(x), lo = bf16(x - hi) ----------------
__global__ void k_split(const float* __restrict__ src,
                        __nv_bfloat16* __restrict__ hi,
                        __nv_bfloat16* __restrict__ lo)
{
    size_t idx = (size_t)blockIdx.x * blockDim.x + threadIdx.x;
    size_t total = (size_t)Nn * Dd;
    size_t stride = (size_t)gridDim.x * blockDim.x;
    for (size_t p = idx; p < total; p += stride) {
        float v = src[p];
        __nv_bfloat16 h = __float2bfloat16_rn(v);
        float hf = __bfloat162float(h);
        hi[p] = h;
        lo[p] = __float2bfloat16_rn(v - hf);
    }
}

// ---------------- HMMA S GEMM: Ab = al*A + (1-al)*relu(Y @ X^T) -------------
// 128x128 tile / CTA, 8 warps of 32x64. K chunks of 64, cp.async dbl-buffer.
// 3-term bf16 split: S ~= Yh Xh^T + Yh Xl^T + Yl Xh^T (fp32 accumulators).
#define SP 72                     // padded smem row stride (bf16 elems)
#define TILE_E (128 * SP)         // one tile: 9216 elems
#define BUF_E (4 * TILE_E)        // Yh,Yl,Xh,Xl
#define S_SMEM_BYTES (2 * BUF_E * 2)
__global__ void __launch_bounds__(256) k_S_mma(
    const float* __restrict__ Aecfp, const float* __restrict__ ra,
    float* __restrict__ Ab)
{
    extern __shared__ __nv_bfloat16 sm[];
    const int tid = threadIdx.x;
    const int wid = tid >> 5;
    const int lane = tid & 31;
    const int g = lane >> 2;           // group id (0..7)
    const int t = lane & 3;            // thread in group
    const int bm = blockIdx.y * 128;
    const int bn = blockIdx.x * 128;
    const int m0 = (wid & 3) * 32;
    const int n0 = (wid >> 2) * 64;

    const uint32_t smem_u32 = smem_to_u32(sm);

    float d[2][8][4];
    #pragma unroll
    for (int i = 0; i < 2; i++)
        #pragma unroll
        for (int j = 0; j < 8; j++)
            #pragma unroll
            for (int e = 0; e < 4; e++) d[i][j][e] = 0.0f;

    const int lrow = tid >> 1;         // 0..127
    const int lhalf = tid & 1;         // 0/1

    auto issue_load = [&](int buf, int kc) {
        const size_t gAoff = (size_t)(bm + lrow) * Dd + kc * 64 + lhalf * 32;
        const size_t gBoff = (size_t)(bn + lrow) * Dd + kc * 64 + lhalf * 32;
        const uint32_t soff = (buf * BUF_E + lrow * SP + lhalf * 32) * 2; // bytes
        #pragma unroll
        for (int q = 0; q < 4; q++) {
            cp_async16(smem_u32 + soff + q * 16,                g_Yh + gAoff + q * 8);
            cp_async16(smem_u32 + soff + TILE_E * 2 + q * 16,   g_Yl + gAoff + q * 8);
            cp_async16(smem_u32 + soff + TILE_E * 4 + q * 16,   g_Xh + gBoff + q * 8);
            cp_async16(smem_u32 + soff + TILE_E * 6 + q * 16,   g_Xl + gBoff + q * 8);
        }
        CP_COMMIT();
    };

    issue_load(0, 0);

    const int NCHUNK = Dd / 64;        // 12
    for (int kc = 0; kc < NCHUNK; kc++) {
        const int buf = kc & 1;
        if (kc + 1 < NCHUNK) { issue_load(buf ^ 1, kc + 1); CP_WAIT(1); }
        else                 { CP_WAIT(0); }
        __syncthreads();

        const __nv_bfloat16* sYh = sm + buf * BUF_E;
        const __nv_bfloat16* sYl = sYh + TILE_E;
        const __nv_bfloat16* sXh = sYl + TILE_E;
        const __nv_bfloat16* sXl = sXh + TILE_E;

        #pragma unroll
        for (int ks = 0; ks < 4; ks++) {
            const int k0 = ks * 16;
            uint32_t ah[2][4], al2[2][4], bh[8][2], bl[8][2];
            #pragma unroll
            for (int ma = 0; ma < 2; ma++) {
                int r = m0 + ma * 16 + g;
                int c = k0 + t * 2;
                ah[ma][0] = *(const uint32_t*)&sYh[r * SP + c];
                ah[ma][1] = *(const uint32_t*)&sYh[(r + 8) * SP + c];
                ah[ma][2] = *(const uint32_t*)&sYh[r * SP + c + 8];
                ah[ma][3] = *(const uint32_t*)&sYh[(r + 8) * SP + c + 8];
                al2[ma][0] = *(const uint32_t*)&sYl[r * SP + c];
                al2[ma][1] = *(const uint32_t*)&sYl[(r + 8) * SP + c];
                al2[ma][2] = *(const uint32_t*)&sYl[r * SP + c + 8];
                al2[ma][3] = *(const uint32_t*)&sYl[(r + 8) * SP + c + 8];
            }
            #pragma unroll
            for (int na = 0; na < 8; na++) {
                int n = n0 + na * 8 + g;
                bh[na][0] = *(const uint32_t*)&sXh[n * SP + k0 + t * 2];
                bh[na][1] = *(const uint32_t*)&sXh[n * SP + k0 + 8 + t * 2];
                bl[na][0] = *(const uint32_t*)&sXl[n * SP + k0 + t * 2];
                bl[na][1] = *(const uint32_t*)&sXl[n * SP + k0 + 8 + t * 2];
            }
            #pragma unroll
            for (int ma = 0; ma < 2; ma++)
                #pragma unroll
                for (int na = 0; na < 8; na++) {
                    mma16816(d[ma][na], ah[ma], bh[na]);   // hi*hi
                    mma16816(d[ma][na], ah[ma], bl[na]);   // hi*lo
                    mma16816(d[ma][na], al2[ma], bh[na]);  // lo*hi
                }
        }
        __syncthreads();
    }

    // epilogue: blend with A_ecfp
    const float alv = sigmoidf(*ra);
    const float om = __fsub_rn(1.0f, alv);

    #pragma unroll
    for (int ma = 0; ma < 2; ma++) {
        #pragma unroll
        for (int na = 0; na < 8; na++) {
            int r = bm + m0 + ma * 16 + g;
            int c = bn + n0 + na * 8 + t * 2;
            size_t base0 = (size_t)r * Nn + c;
            size_t base1 = (size_t)(r + 8) * Nn + c;
            float2 av0 = *reinterpret_cast<const float2*>(&Aecfp[base0]);
            float2 av1 = *reinterpret_cast<const float2*>(&Aecfp[base1]);
            float2 o0, o1;
            o0.x = __fadd_rn(__fmul_rn(alv, av0.x), __fmul_rn(om, fmaxf(d[ma][na][0], 0.0f)));
            o0.y = __fadd_rn(__fmul_rn(alv, av0.y), __fmul_rn(om, fmaxf(d[ma][na][1], 0.0f)));
            o1.x = __fadd_rn(__fmul_rn(alv, av1.x), __fmul_rn(om, fmaxf(d[ma][na][2], 0.0f)));
            o1.y = __fadd_rn(__fmul_rn(alv, av1.y), __fmul_rn(om, fmaxf(d[ma][na][3], 0.0f)));
            *reinterpret_cast<float2*>(&Ab[base0]) = o0;
            *reinterpret_cast<float2*>(&Ab[base1]) = o1;
        }
    }
}

// ---------------- 128x128x16 double-buffered f32x2 GEMM (verified R5) --------
// EP 0: C = acc ; EP 1: C = gelu(acc+bias) ; EP 2: C = resid + gelu(acc*rs+bias)
template <int EP>
__global__ void __launch_bounds__(256, 2) k_gemm128(
    const float* __restrict__ A, const float* __restrict__ B,
    float* __restrict__ C, int Nc, int Kc,
    const float* __restrict__ bias,
    const float* __restrict__ rowsum,
    const float* __restrict__ resid)
{
    __shared__ float As[2][16][128];
    __shared__ float Bs[2][16][128];

    const int bm = blockIdx.y * 128;
    const int bn = blockIdx.x * 128;
    const int tid = threadIdx.x;
    const int tr = tid >> 4;
    const int tc = tid & 15;

    ull acc2[8][4];
    #pragma unroll
    for (int i = 0; i < 8; i++)
        #pragma unroll
        for (int j = 0; j < 4; j++) acc2[i][j] = 0ULL;

    float4 pa[2], pb[2];

    auto loadG = [&](int k0) {
        #pragma unroll
        for (int l = 0; l < 2; l++) {
            int idx = tid + l * 256;
            int m = idx >> 2, kq = idx & 3;
            pa[l] = *reinterpret_cast<const float4*>(
                &A[(size_t)(bm + m) * Kc + k0 + kq * 4]);
        }
        #pragma unroll
        for (int l = 0; l < 2; l++) {
            int idx = tid + l * 256;
            int k = idx >> 5, nq = idx & 31;
            pb[l] = *reinterpret_cast<const float4*>(
                &B[(size_t)(k0 + k) * Nc + bn + nq * 4]);
        }
    };
    auto storeS = [&](int buf) {
        #pragma unroll
        for (int l = 0; l < 2; l++) {
            int idx = tid + l * 256;
            int m = idx >> 2, kq = idx & 3;
            As[buf][kq * 4 + 0][m] = pa[l].x;
            As[buf][kq * 4 + 1][m] = pa[l].y;
            As[buf][kq * 4 + 2][m] = pa[l].z;
            As[buf][kq * 4 + 3][m] = pa[l].w;
        }
        #pragma unroll
        for (int l = 0; l < 2; l++) {
            int idx = tid + l * 256;
            int k = idx >> 5, nq = idx & 31;
            *reinterpret_cast<float4*>(&Bs[buf][k][nq * 4]) = pb[l];
        }
    };
    auto compute = [&](int buf) {
        #pragma unroll
        for (int k = 0; k < 16; k++) {
            float4 a0 = *reinterpret_cast<const float4*>(&As[buf][k][tr * 4]);
            float4 a1 = *reinterpret_cast<const float4*>(&As[buf][k][64 + tr * 4]);
            float4 b0 = *reinterpret_cast<const float4*>(&Bs[buf][k][tc * 4]);
            float4 b1 = *reinterpret_cast<const float4*>(&Bs[buf][k][64 + tc * 4]);
            ull bp[4] = {pack2(b0.x, b0.y), pack2(b0.z, b0.w),
                         pack2(b1.x, b1.y), pack2(b1.z, b1.w)};
            float av[8] = {a0.x, a0.y, a0.z, a0.w, a1.x, a1.y, a1.z, a1.w};
            #pragma unroll
            for (int i = 0; i < 8; i++) {
                ull ap = pack2(av[i], av[i]);
                #pragma unroll
                for (int j = 0; j < 4; j++) fma2(acc2[i][j], ap, bp[j]);
            }
        }
    };

    loadG(0);
    storeS(0);
    __syncthreads();
    int buf = 0;
    for (int k0 = 16; k0 < Kc; k0 += 16) {
        loadG(k0);
        compute(buf);
        storeS(1 - buf);
        __syncthreads();
        buf ^= 1;
    }
    compute(buf);

    #pragma unroll
    for (int i = 0; i < 8; i++) {
        int row = bm + ((i < 4) ? (tr * 4 + i) : (64 + tr * 4 + (i - 4)));
        float c[8];
        unpack2(acc2[i][0], c[0], c[1]);
        unpack2(acc2[i][1], c[2], c[3]);
        unpack2(acc2[i][2], c[4], c[5]);
        unpack2(acc2[i][3], c[6], c[7]);

        float rs = 1.0f;
        if (EP == 2) rs = 1.0f / fmaxf(rowsum[row], 1e-8f);

        #pragma unroll
        for (int gg = 0; gg < 2; gg++) {
            int col0 = bn + gg * 64 + tc * 4;
            size_t base = (size_t)row * Nc + col0;
            float4 o;
            float* po = &o.x;
            #pragma unroll
            for (int j = 0; j < 4; j++) {
                float v = c[gg * 4 + j];
                if (EP == 2) v *= rs;
                if (EP == 1 || EP == 2) v = geluf(v + bias[col0 + j]);
                if (EP == 2) v += resid[base + j];
                po[j] = v;
            }
            *reinterpret_cast<float4*>(&C[base]) = o;
        }
    }
}

// ---------------- per-row top-K (threshold quick-reject, float4) ------------
__global__ void k_topk2()
{
    __shared__ ull cand[256 * KK];
    __shared__ ull red[256];

    const int row = blockIdx.x;
    const int tid = threadIdx.x;
    const float4* src = reinterpret_cast<const float4*>(&g_Ab[(size_t)row * Nn]);

    ull loc[KK];
    float locv[KK];
    #pragma unroll
    for (int t = 0; t < KK; t++) { loc[t] = 0ULL; locv[t] = -1e30f; }
    float vth = -1e30f;

    for (int q = tid; q < Nn / 4; q += 256) {
        float4 v = src[q];
        float vv[4] = {v.x, v.y, v.z, v.w};
        #pragma unroll
        for (int e = 0; e < 4; e++) {
            float f = vv[e];
            if (f > vth) {
                int j = q * 4 + e;
                unsigned u = __float_as_uint(f);
                u ^= (u >> 31) ? 0xFFFFFFFFu : 0x80000000u;
                ull key = ((ull)u << 32) | (ull)(0xFFFFFFFFu - (unsigned)j);
                loc[KK - 1] = key; locv[KK - 1] = f;
                #pragma unroll
                for (int t = KK - 1; t > 0; t--) {
                    if (loc[t] > loc[t - 1]) {
                        ull tk = loc[t]; loc[t] = loc[t - 1]; loc[t - 1] = tk;
                        float tv = locv[t]; locv[t] = locv[t - 1]; locv[t - 1] = tv;
                    }
                }
                vth = locv[KK - 1];
            }
        }
    }
    #pragma unroll
    for (int t = 0; t < KK; t++) cand[tid * KK + t] = loc[t];
    __syncthreads();

    for (int t = 0; t < KK; t++) {
        ull m = 0ULL;
        for (int p = tid; p < 256 * KK; p += 256)
            if (cand[p] > m) m = cand[p];
        red[tid] = m;
        __syncthreads();
        for (int s = 128; s > 0; s >>= 1) {
            if (tid < s && red[tid + s] > red[tid]) red[tid] = red[tid + s];
            __syncthreads();
        }
        ull best = red[0];
        if (tid == 0)
            g_top[row * KK + t] = (int)(0xFFFFFFFFu - (unsigned)(best & 0xFFFFFFFFULL));
        for (int p = tid; p < 256 * KK; p += 256)
            if (cand[p] == best) cand[p] = 0ULL;
        __syncthreads();
    }
}

// ---------------- head tail ---------------------------------------------------
__global__ void k_head_tail(const float* __restrict__ wh, const float* __restrict__ bh,
                            float* __restrict__ out, int computeG,
                            const float* __restrict__ gam)
{
    __shared__ float swh[4 * H2s];
    for (int i = threadIdx.x; i < 4 * H2s; i += blockDim.x) {
        int c = i >> 8, d = i & 255;
        swh[i] = wh[d * 4 + c];
    }
    __syncthreads();

    const int warp = threadIdx.x >> 5;
    const int lane = threadIdx.x & 31;
    const int row = blockIdx.x * 8 + warp;

    float a0 = 0.f, a1 = 0.f, a2 = 0.f, a3 = 0.f;
    for (int d = lane; d < H2s; d += 32) {
        float v = g_L2[(size_t)row * H2s + d];
        a0 += v * swh[0 * H2s + d];
        a1 += v * swh[1 * H2s + d];
        a2 += v * swh[2 * H2s + d];
        a3 += v * swh[3 * H2s + d];
    }
    #pragma unroll
    for (int off = 16; off > 0; off >>= 1) {
        a0 += __shfl_xor_sync(0xffffffffu, a0, off);
        a1 += __shfl_xor_sync(0xffffffffu, a1, off);
        a2 += __shfl_xor_sync(0xffffffffu, a2, off);
        a3 += __shfl_xor_sync(0xffffffffu, a3, off);
    }
    if (lane == 0) {
        float r0 = a0 + bh[0], r1 = a1 + bh[1], r2 = a2 + bh[2], r3 = a3 + bh[3];
        float m  = r0;
        float vv = softplusf(r1) + 1e-6f;
        float aa = softplusf(r2) + 1.0f + 1e-6f;
        float bb = softplusf(r3) + 1e-6f;
        out[row]          = m;
        out[Nn + row]     = vv;
        out[2 * Nn + row] = aa;
        out[3 * Nn + row] = bb;
        if (computeG) {
            float u0 = bb / fmaxf(aa - 1.0f, 1e-8f);
            g_G[row] = 1.0f - (*gam) * sigmoidf(u0);
        }
    }
}

// ---------------- mask construction ------------------------------------------
__global__ void k_zero_mask()
{
    size_t idx = (size_t)blockIdx.x * blockDim.x + threadIdx.x;
    size_t total = (size_t)Nn * 256;
    size_t stride = (size_t)gridDim.x * blockDim.x;
    for (size_t p = idx; p < total; p += stride) g_mask[p] = 0u;
}

__global__ void k_set_mask()
{
    int e = blockIdx.x * blockDim.x + threadIdx.x;
    if (e >= Nn * KK) return;
    int i = e / KK;
    int j = g_top[e];
    if (j == i) return;
    atomicOr(&g_mask[i * 256 + (j >> 5)], 1u << (j & 31));
    atomicOr(&g_mask[j * 256 + (i >> 5)], 1u << (i & 31));
}

// ---------------- sparse per-row aggregation (deterministic) -----------------
#define EB 2048
__global__ void k_edges(const float* __restrict__ X)
{
    __shared__ unsigned int mwords[256];
    __shared__ int sc[256];
    __shared__ int lst[EB];
    __shared__ float cf[EB];
    __shared__ float abv[EB];
    __shared__ float s_rowsum;

    const int row = blockIdx.x;
    const int tid = threadIdx.x;

    unsigned int w0 = g_mask[row * 256 + tid];
    mwords[tid] = w0;
    int myp = __popc(w0);
    sc[tid] = myp;
    __syncthreads();
    for (int off = 1; off < 256; off <<= 1) {
        int v = (tid >= off) ? sc[tid - off] : 0;
        __syncthreads();
        sc[tid] += v;
        __syncthreads();
    }
    const int myoff = sc[tid] - myp;
    const int E = sc[255];
    if (tid == 0) s_rowsum = 0.0f;
    __syncthreads();

    float racc0 = 0.f, racc1 = 0.f, racc2 = 0.f;

    for (int start = 0; start < E; start += EB) {
        int end = (E < start + EB) ? E : (start + EB);
        int cnt = end - start;
        {
            unsigned int w = mwords[tid];
            int pos = myoff;
            while (w) {
                int b = __ffs(w) - 1;
                w &= w - 1;
                if (pos >= start && pos < end) lst[pos - start] = tid * 32 + b;
                pos++;
            }
        }
        __syncthreads();
        for (int e = tid; e < cnt; e += 256) {
            int j = lst[e];
            float ab = g_Ab[(size_t)row * Nn + j];
            abv[e] = ab;
            cf[e] = ab * g_G[j];
        }
        __syncthreads();
        if (tid == 0) {
            float s = s_rowsum;
            for (int e = 0; e < cnt; e++) s += abv[e];
            s_rowsum = s;
        }
        for (int e = 0; e < cnt; e++) {
            float c = cf[e];
            const float* xr = &X[(size_t)lst[e] * Dd];
            racc0 += c * xr[tid];
            racc1 += c * xr[tid + 256];
            racc2 += c * xr[tid + 512];
        }
        __syncthreads();
    }

    g_Agg[(size_t)row * Dd + tid]       = racc0;
    g_Agg[(size_t)row * Dd + tid + 256] = racc1;
    g_Agg[(size_t)row * Dd + tid + 512] = racc2;
    if (tid == 0) g_rowsum[row] = s_rowsum;
}

// ---------------- launch ----------------------------------------------------
extern "C" void kernel_launch(void* const* d_in, const int* in_sizes, int n_in,
                              void* d_out, int out_size)
{
    const float* X     = (const float*)d_in[0];
    const float* A     = (const float*)d_in[1];
    const float* W_gm  = (const float*)d_in[2];
    const float* ra    = (const float*)d_in[3];
    const float* gam   = (const float*)d_in[4];
    const float* ih_w1 = (const float*)d_in[5];
    const float* ih_b1 = (const float*)d_in[6];
    const float* ih_w2 = (const float*)d_in[7];
    const float* ih_b2 = (const float*)d_in[8];
    const float* ih_wh = (const float*)d_in[9];
    const float* ih_bh = (const float*)d_in[10];
    const float* gcn_w = (const float*)d_in[11];
    const float* gcn_b = (const float*)d_in[12];
    const float* fh_w1 = (const float*)d_in[13];
    const float* fh_b1 = (const float*)d_in[14];
    const float* fh_w2 = (const float*)d_in[15];
    const float* fh_b2 = (const float*)d_in[16];
    const float* fh_wh = (const float*)d_in[17];
    const float* fh_bh = (const float*)d_in[18];
    float* out = (float*)d_out;

    static float *pY = nullptr, *pAb = nullptr, *pL1 = nullptr, *pL2 = nullptr,
                 *pAgg = nullptr, *pXp = nullptr, *pRs = nullptr;
    static __nv_bfloat16 *pYh = nullptr, *pYl = nullptr, *pXh = nullptr, *pXl = nullptr;
    if (!pY) {
        cudaGetSymbolAddress((void**)&pY,  g_Y);
        cudaGetSymbolAddress((void**)&pAb, g_Ab);
        cudaGetSymbolAddress((void**)&pL1, g_L1);
        cudaGetSymbolAddress((void**)&pL2, g_L2);
        cudaGetSymbolAddress((void**)&pAgg, g_Agg);
        cudaGetSymbolAddress((void**)&pXp, g_Xp);
        cudaGetSymbolAddress((void**)&pRs, g_rowsum);
        cudaGetSymbolAddress((void**)&pYh, g_Yh);
        cudaGetSymbolAddress((void**)&pYl, g_Yl);
        cudaGetSymbolAddress((void**)&pXh, g_Xh);
        cudaGetSymbolAddress((void**)&pXl, g_Xl);
        cudaFuncSetAttribute(k_S_mma, cudaFuncAttributeMaxDynamicSharedMemorySize,
                             S_SMEM_BYTES);
    }

    dim3 blk(256);

    // 1. Y = X @ W_gm (fp32, f32x2)
    k_gemm128<0><<<dim3(Dd / 128, Nn / 128), blk>>>(
        X, W_gm, pY, Dd, Dd, nullptr, nullptr, nullptr);

    // 2. bf16 splits of Y and X
    k_split<<<4096, blk>>>(pY, pYh, pYl);
    k_split<<<4096, blk>>>(X, pXh, pXl);

    // 3. Ab = al*A + (1-al)*relu(Y @ X^T)  via HMMA bf16 3-term split
    k_S_mma<<<dim3(Nn / 128, Nn / 128), blk, S_SMEM_BYTES>>>(A, ra, pAb);

    // 4. per-row top-5
    k_topk2<<<Nn, blk>>>();

    // 5. union mask
    k_zero_mask<<<2048, blk>>>();
    k_set_mask<<<(Nn * KK + 255) / 256, blk>>>();

    // 6. NIG head 1 on X -> out[0..4N) and gate G
    k_gemm128<1><<<dim3(H1s / 128, Nn / 128), blk>>>(
        X, ih_w1, pL1, H1s, Dd, ih_b1, nullptr, nullptr);
    k_gemm128<1><<<dim3(H2s / 128, Nn / 128), blk>>>(
        pL1, ih_w2, pL2, H2s, H1s, ih_b2, nullptr, nullptr);
    k_head_tail<<<Nn / 8, blk>>>(ih_wh, ih_bh, out, 1, gam);

    // 7. sparse aggregation: Agg, rowsum
    k_edges<<<Nn, blk>>>(X);

    // 8. Xp = X + gelu((Agg / rowsum) @ gcn_w + gcn_b)
    k_gemm128<2><<<dim3(Dd / 128, Nn / 128), blk>>>(
        pAgg, gcn_w, pXp, Dd, Dd, gcn_b, pRs, X);

    // 9. NIG head 2 on Xp -> out[4N..8N)
    k_gemm128<1><<<dim3(H1s / 128, Nn / 128), blk>>>(
        pXp, fh_w1, pL1, H1s, Dd, fh_b1, nullptr, nullptr);
    k_gemm128<1><<<dim3(H2s / 128, Nn / 128), blk>>>(
        pL1, fh_w2, pL2, H2s, H1s, fh_b2, nullptr, nullptr);
    k_head_tail<<<Nn / 8, blk>>>(fh_wh, fh_bh, out + 4 * Nn, 0, nullptr);
}

// round 8
// speedup vs baseline: 3.7299x; 1.1374x over previous
#include <cuda_runtime.h>
#include <cuda_bf16.h>
#include <math.h>
#include <stdint.h>

#define Nn 8192
#define Dd 768
#define H1s 512
#define H2s 256
#define KK 5

typedef unsigned long long ull;
typedef __nv_bfloat16 bf16;
typedef __nv_bfloat162 bf162;

// ---------------- scratch (device globals; no allocation allowed) ----------
__device__ float g_Ab[67108864];            // blended score matrix (N x N)
__device__ float g_L2[Nn * H2s];            // fp32 (head_tail input)
__device__ float g_G[Nn];
__device__ int   g_top[Nn * KK];
__device__ float g_rowsum[Nn];
__device__ unsigned int g_mask[Nn * 256];

__device__ bf16 g_Xh[Nn * Dd],  g_Xl[Nn * Dd];
__device__ bf16 g_Yh[Nn * Dd],  g_Yl[Nn * Dd];
__device__ bf16 g_L1h[Nn * H1s], g_L1l[Nn * H1s];
__device__ bf16 g_Xph[Nn * Dd], g_Xpl[Nn * Dd];
__device__ bf16 g_Aggh[Nn * Dd], g_Aggl[Nn * Dd];
__device__ bf16 g_WgmTh[Dd * Dd], g_WgmTl[Dd * Dd];
__device__ bf16 g_W1aTh[H1s * Dd], g_W1aTl[H1s * Dd];
__device__ bf16 g_W2aTh[H2s * H1s], g_W2aTl[H2s * H1s];
__device__ bf16 g_GcnTh[Dd * Dd], g_GcnTl[Dd * Dd];
__device__ bf16 g_W1bTh[H1s * Dd], g_W1bTl[H1s * Dd];
__device__ bf16 g_W2bTh[H2s * H1s], g_W2bTl[H2s * H1s];

// ---------------- math helpers ---------------------------------------------
__device__ __forceinline__ float geluf(float x) {
    return 0.5f * x * (1.0f + erff(x * 0.70710678118654752f));
}
__device__ __forceinline__ float softplusf(float x) {
    return fmaxf(x, 0.0f) + log1pf(expf(-fabsf(x)));
}
__device__ __forceinline__ float sigmoidf(float x) {
    return 1.0f / (1.0f + expf(-x));
}

// ---------------- HMMA m16n8k16 bf16 wrapper ---------------------------------
__device__ __forceinline__ void mma16816(float* d, const uint32_t* a, const uint32_t* b) {
    asm volatile(
        "mma.sync.aligned.m16n8k16.row.col.f32.bf16.bf16.f32 "
        "{%0,%1,%2,%3}, {%4,%5,%6,%7}, {%8,%9}, {%0,%1,%2,%3};"
        : "+f"(d[0]), "+f"(d[1]), "+f"(d[2]), "+f"(d[3])
        : "r"(a[0]), "r"(a[1]), "r"(a[2]), "r"(a[3]), "r"(b[0]), "r"(b[1]));
}
__device__ __forceinline__ uint32_t smem_to_u32(const void* p) {
    uint32_t a;
    asm("{ .reg .u64 t; cvta.to.shared.u64 t, %1; cvt.u32.u64 %0, t; }"
        : "=r"(a) : "l"(p));
    return a;
}
__device__ __forceinline__ void cp_async16(uint32_t dst, const void* src) {
    asm volatile("cp.async.cg.shared.global [%0], [%1], 16;"
                 :: "r"(dst), "l"(src) : "memory");
}
#define CP_COMMIT() asm volatile("cp.async.commit_group;" ::: "memory")
#define CP_WAIT(n)  asm volatile("cp.async.wait_group %0;" :: "n"(n) : "memory")

__device__ __forceinline__ void write_split(bf16* Ch, bf16* Cl, size_t idx,
                                            float v0, float v1) {
    bf16 h0 = __float2bfloat16_rn(v0);
    bf16 h1 = __float2bfloat16_rn(v1);
    bf162 hh; hh.x = h0; hh.y = h1;
    *reinterpret_cast<bf162*>(Ch + idx) = hh;
    bf162 ll;
    ll.x = __float2bfloat16_rn(v0 - __bfloat162float(h0));
    ll.y = __float2bfloat16_rn(v1 - __bfloat162float(h1));
    *reinterpret_cast<bf162*>(Cl + idx) = ll;
}

// ---------------- bf16 split of a fp32 matrix --------------------------------
__global__ void k_split(const float* __restrict__ src,
                        bf16* __restrict__ hi, bf16* __restrict__ lo, size_t total)
{
    size_t idx = (size_t)blockIdx.x * blockDim.x + threadIdx.x;
    size_t stride = (size_t)gridDim.x * blockDim.x;
    for (size_t p = idx; p < total; p += stride) {
        float v = src[p];
        bf16 h = __float2bfloat16_rn(v);
        hi[p] = h;
        lo[p] = __float2bfloat16_rn(v - __bfloat162float(h));
    }
}

// ---------------- transpose + bf16 split of weight: wT[n][k] = w[k][n] ------
__global__ void k_tsplit(const float* __restrict__ w,
                         bf16* __restrict__ th, bf16* __restrict__ tl,
                         int K, int N)
{
    __shared__ float t[32][33];
    const int bx = blockIdx.x * 32;   // along N
    const int by = blockIdx.y * 32;   // along K
    #pragma unroll
    for (int dy = 0; dy < 32; dy += 8)
        t[threadIdx.y + dy][threadIdx.x] =
            w[(size_t)(by + threadIdx.y + dy) * N + bx + threadIdx.x];
    __syncthreads();
    #pragma unroll
    for (int dy = 0; dy < 32; dy += 8) {
        float v = t[threadIdx.x][threadIdx.y + dy];
        size_t o = (size_t)(bx + threadIdx.y + dy) * K + by + threadIdx.x;
        bf16 h = __float2bfloat16_rn(v);
        th[o] = h;
        tl[o] = __float2bfloat16_rn(v - __bfloat162float(h));
    }
}

// ---------------- unified HMMA NT GEMM (bf16 3-term split, fp32 accum) ------
// C[M,Nc] = A[M,Kc] @ B[Nc,Kc]^T.  128x128 tile/CTA, 8 warps of 32x64,
// K chunks of 64 with cp.async double buffering. Kc % 64 == 0.
// EP 0: Cf = al*Aecfp + (1-al)*relu(acc)                 (S blend)
// EP 1: split(gelu(acc + bias))                          (L1)
// EP 2: Cf = gelu(acc + bias)                            (L2, fp32)
// EP 3: split(resid + gelu(acc/max(rowsum,1e-8) + bias)) (gcn -> Xp)
// EP 4: split(acc)                                       (Y)
#define SP 72
#define TILE_E (128 * SP)
#define BUF_E (4 * TILE_E)
#define S_SMEM_BYTES (2 * BUF_E * 2)
template <int EP>
__global__ void __launch_bounds__(256) k_hmma(
    const bf16* __restrict__ Ah, const bf16* __restrict__ Al,
    const bf16* __restrict__ Bh, const bf16* __restrict__ Bl,
    float* __restrict__ Cf, bf16* __restrict__ Ch, bf16* __restrict__ Cl,
    int Nc, int Kc,
    const float* __restrict__ bias,
    const float* __restrict__ rowsum,
    const float* __restrict__ resid,
    const float* __restrict__ Aecfp,
    const float* __restrict__ ra)
{
    extern __shared__ bf16 sm[];
    const int tid = threadIdx.x;
    const int wid = tid >> 5;
    const int lane = tid & 31;
    const int g = lane >> 2;
    const int t = lane & 3;
    const int bm = blockIdx.y * 128;
    const int bn = blockIdx.x * 128;
    const int m0 = (wid & 3) * 32;
    const int n0 = (wid >> 2) * 64;

    const uint32_t smem_u32 = smem_to_u32(sm);

    float d[2][8][4];
    #pragma unroll
    for (int i = 0; i < 2; i++)
        #pragma unroll
        for (int j = 0; j < 8; j++)
            #pragma unroll
            for (int e = 0; e < 4; e++) d[i][j][e] = 0.0f;

    const int lrow = tid >> 1;
    const int lhalf = tid & 1;

    auto issue_load = [&](int buf, int kc) {
        const size_t gAoff = (size_t)(bm + lrow) * Kc + kc * 64 + lhalf * 32;
        const size_t gBoff = (size_t)(bn + lrow) * Kc + kc * 64 + lhalf * 32;
        const uint32_t soff = (buf * BUF_E + lrow * SP + lhalf * 32) * 2;
        #pragma unroll
        for (int q = 0; q < 4; q++) {
            cp_async16(smem_u32 + soff + q * 16,              Ah + gAoff + q * 8);
            cp_async16(smem_u32 + soff + TILE_E * 2 + q * 16, Al + gAoff + q * 8);
            cp_async16(smem_u32 + soff + TILE_E * 4 + q * 16, Bh + gBoff + q * 8);
            cp_async16(smem_u32 + soff + TILE_E * 6 + q * 16, Bl + gBoff + q * 8);
        }
        CP_COMMIT();
    };

    issue_load(0, 0);

    const int NCHUNK = Kc / 64;
    for (int kc = 0; kc < NCHUNK; kc++) {
        const int buf = kc & 1;
        if (kc + 1 < NCHUNK) { issue_load(buf ^ 1, kc + 1); CP_WAIT(1); }
        else                 { CP_WAIT(0); }
        __syncthreads();

        const bf16* sYh = sm + buf * BUF_E;
        const bf16* sYl = sYh + TILE_E;
        const bf16* sXh = sYl + TILE_E;
        const bf16* sXl = sXh + TILE_E;

        #pragma unroll
        for (int ks = 0; ks < 4; ks++) {
            const int k0 = ks * 16;
            uint32_t ah[2][4], al2[2][4], bh[8][2], bl[8][2];
            #pragma unroll
            for (int ma = 0; ma < 2; ma++) {
                int r = m0 + ma * 16 + g;
                int c = k0 + t * 2;
                ah[ma][0] = *(const uint32_t*)&sYh[r * SP + c];
                ah[ma][1] = *(const uint32_t*)&sYh[(r + 8) * SP + c];
                ah[ma][2] = *(const uint32_t*)&sYh[r * SP + c + 8];
                ah[ma][3] = *(const uint32_t*)&sYh[(r + 8) * SP + c + 8];
                al2[ma][0] = *(const uint32_t*)&sYl[r * SP + c];
                al2[ma][1] = *(const uint32_t*)&sYl[(r + 8) * SP + c];
                al2[ma][2] = *(const uint32_t*)&sYl[r * SP + c + 8];
                al2[ma][3] = *(const uint32_t*)&sYl[(r + 8) * SP + c + 8];
            }
            #pragma unroll
            for (int na = 0; na < 8; na++) {
                int n = n0 + na * 8 + g;
                bh[na][0] = *(const uint32_t*)&sXh[n * SP + k0 + t * 2];
                bh[na][1] = *(const uint32_t*)&sXh[n * SP + k0 + 8 + t * 2];
                bl[na][0] = *(const uint32_t*)&sXl[n * SP + k0 + t * 2];
                bl[na][1] = *(const uint32_t*)&sXl[n * SP + k0 + 8 + t * 2];
            }
            // term-outer ordering: 16 independent MMAs between same-acc reuse
            #pragma unroll
            for (int ma = 0; ma < 2; ma++)
                #pragma unroll
                for (int na = 0; na < 8; na++)
                    mma16816(d[ma][na], ah[ma], bh[na]);
            #pragma unroll
            for (int ma = 0; ma < 2; ma++)
                #pragma unroll
                for (int na = 0; na < 8; na++)
                    mma16816(d[ma][na], ah[ma], bl[na]);
            #pragma unroll
            for (int ma = 0; ma < 2; ma++)
                #pragma unroll
                for (int na = 0; na < 8; na++)
                    mma16816(d[ma][na], al2[ma], bh[na]);
        }
        __syncthreads();
    }

    // ---- epilogue
    float alv = 0.f, om = 0.f;
    if (EP == 0) { alv = sigmoidf(*ra); om = __fsub_rn(1.0f, alv); }

    #pragma unroll
    for (int ma = 0; ma < 2; ma++) {
        #pragma unroll
        for (int na = 0; na < 8; na++) {
            const int r = bm + m0 + ma * 16 + g;
            const int c = bn + n0 + na * 8 + t * 2;
            const size_t i0 = (size_t)r * Nc + c;
            const size_t i1 = (size_t)(r + 8) * Nc + c;
            float v0 = d[ma][na][0], v1 = d[ma][na][1];
            float v2 = d[ma][na][2], v3 = d[ma][na][3];

            if (EP == 0) {
                float2 a0 = *reinterpret_cast<const float2*>(&Aecfp[i0]);
                float2 a1 = *reinterpret_cast<const float2*>(&Aecfp[i1]);
                float2 o0, o1;
                o0.x = __fadd_rn(__fmul_rn(alv, a0.x), __fmul_rn(om, fmaxf(v0, 0.0f)));
                o0.y = __fadd_rn(__fmul_rn(alv, a0.y), __fmul_rn(om, fmaxf(v1, 0.0f)));
                o1.x = __fadd_rn(__fmul_rn(alv, a1.x), __fmul_rn(om, fmaxf(v2, 0.0f)));
                o1.y = __fadd_rn(__fmul_rn(alv, a1.y), __fmul_rn(om, fmaxf(v3, 0.0f)));
                *reinterpret_cast<float2*>(&Cf[i0]) = o0;
                *reinterpret_cast<float2*>(&Cf[i1]) = o1;
            } else if (EP == 4) {
                write_split(Ch, Cl, i0, v0, v1);
                write_split(Ch, Cl, i1, v2, v3);
            } else {
                const float b0 = bias[c], b1 = bias[c + 1];
                if (EP == 3) {
                    float rs0 = 1.0f / fmaxf(rowsum[r], 1e-8f);
                    float rs1 = 1.0f / fmaxf(rowsum[r + 8], 1e-8f);
                    v0 *= rs0; v1 *= rs0; v2 *= rs1; v3 *= rs1;
                }
                v0 = geluf(v0 + b0); v1 = geluf(v1 + b1);
                v2 = geluf(v2 + b0); v3 = geluf(v3 + b1);
                if (EP == 3) {
                    float2 r0 = *reinterpret_cast<const float2*>(&resid[i0]);
                    float2 r1 = *reinterpret_cast<const float2*>(&resid[i1]);
                    v0 += r0.x; v1 += r0.y; v2 += r1.x; v3 += r1.y;
                }
                if (EP == 2) {
                    float2 o0 = {v0, v1}, o1 = {v2, v3};
                    *reinterpret_cast<float2*>(&Cf[i0]) = o0;
                    *reinterpret_cast<float2*>(&Cf[i1]) = o1;
                } else {
                    write_split(Ch, Cl, i0, v0, v1);
                    write_split(Ch, Cl, i1, v2, v3);
                }
            }
        }
    }
}

// ---------------- per-row top-K (threshold quick-reject, float4) ------------
__global__ void k_topk2()
{
    __shared__ ull cand[256 * KK];
    __shared__ ull red[256];

    const int row = blockIdx.x;
    const int tid = threadIdx.x;
    const float4* src = reinterpret_cast<const float4*>(&g_Ab[(size_t)row * Nn]);

    ull loc[KK];
    float locv[KK];
    #pragma unroll
    for (int t = 0; t < KK; t++) { loc[t] = 0ULL; locv[t] = -1e30f; }
    float vth = -1e30f;

    for (int q = tid; q < Nn / 4; q += 256) {
        float4 v = src[q];
        float vv[4] = {v.x, v.y, v.z, v.w};
        #pragma unroll
        for (int e = 0; e < 4; e++) {
            float f = vv[e];
            if (f > vth) {
                int j = q * 4 + e;
                unsigned u = __float_as_uint(f);
                u ^= (u >> 31) ? 0xFFFFFFFFu : 0x80000000u;
                ull key = ((ull)u << 32) | (ull)(0xFFFFFFFFu - (unsigned)j);
                loc[KK - 1] = key; locv[KK - 1] = f;
                #pragma unroll
                for (int t = KK - 1; t > 0; t--) {
                    if (loc[t] > loc[t - 1]) {
                        ull tk = loc[t]; loc[t] = loc[t - 1]; loc[t - 1] = tk;
                        float tv = locv[t]; locv[t] = locv[t - 1]; locv[t - 1] = tv;
                    }
                }
                vth = locv[KK - 1];
            }
        }
    }
    #pragma unroll
    for (int t = 0; t < KK; t++) cand[tid * KK + t] = loc[t];
    __syncthreads();

    for (int t = 0; t < KK; t++) {
        ull m = 0ULL;
        for (int p = tid; p < 256 * KK; p += 256)
            if (cand[p] > m) m = cand[p];
        red[tid] = m;
        __syncthreads();
        for (int s = 128; s > 0; s >>= 1) {
            if (tid < s && red[tid + s] > red[tid]) red[tid] = red[tid + s];
            __syncthreads();
        }
        ull best = red[0];
        if (tid == 0)
            g_top[row * KK + t] = (int)(0xFFFFFFFFu - (unsigned)(best & 0xFFFFFFFFULL));
        for (int p = tid; p < 256 * KK; p += 256)
            if (cand[p] == best) cand[p] = 0ULL;
        __syncthreads();
    }
}

// ---------------- head tail ---------------------------------------------------
__global__ void k_head_tail(const float* __restrict__ wh, const float* __restrict__ bh,
                            float* __restrict__ out, int computeG,
                            const float* __restrict__ gam)
{
    __shared__ float swh[4 * H2s];
    for (int i = threadIdx.x; i < 4 * H2s; i += blockDim.x) {
        int c = i >> 8, d = i & 255;
        swh[i] = wh[d * 4 + c];
    }
    __syncthreads();

    const int warp = threadIdx.x >> 5;
    const int lane = threadIdx.x & 31;
    const int row = blockIdx.x * 8 + warp;

    float a0 = 0.f, a1 = 0.f, a2 = 0.f, a3 = 0.f;
    for (int d = lane; d < H2s; d += 32) {
        float v = g_L2[(size_t)row * H2s + d];
        a0 += v * swh[0 * H2s + d];
        a1 += v * swh[1 * H2s + d];
        a2 += v * swh[2 * H2s + d];
        a3 += v * swh[3 * H2s + d];
    }
    #pragma unroll
    for (int off = 16; off > 0; off >>= 1) {
        a0 += __shfl_xor_sync(0xffffffffu, a0, off);
        a1 += __shfl_xor_sync(0xffffffffu, a1, off);
        a2 += __shfl_xor_sync(0xffffffffu, a2, off);
        a3 += __shfl_xor_sync(0xffffffffu, a3, off);
    }
    if (lane == 0) {
        float r0 = a0 + bh[0], r1 = a1 + bh[1], r2 = a2 + bh[2], r3 = a3 + bh[3];
        float m  = r0;
        float vv = softplusf(r1) + 1e-6f;
        float aa = softplusf(r2) + 1.0f + 1e-6f;
        float bb = softplusf(r3) + 1e-6f;
        out[row]          = m;
        out[Nn + row]     = vv;
        out[2 * Nn + row] = aa;
        out[3 * Nn + row] = bb;
        if (computeG) {
            float u0 = bb / fmaxf(aa - 1.0f, 1e-8f);
            g_G[row] = 1.0f - (*gam) * sigmoidf(u0);
        }
    }
}

// ---------------- mask construction ------------------------------------------
__global__ void k_zero_mask()
{
    size_t idx = (size_t)blockIdx.x * blockDim.x + threadIdx.x;
    size_t total = (size_t)Nn * 256;
    size_t stride = (size_t)gridDim.x * blockDim.x;
    for (size_t p = idx; p < total; p += stride) g_mask[p] = 0u;
}

__global__ void k_set_mask()
{
    int e = blockIdx.x * blockDim.x + threadIdx.x;
    if (e >= Nn * KK) return;
    int i = e / KK;
    int j = g_top[e];
    if (j == i) return;
    atomicOr(&g_mask[i * 256 + (j >> 5)], 1u << (j & 31));
    atomicOr(&g_mask[j * 256 + (i >> 5)], 1u << (i & 31));
}

// ---------------- sparse per-row aggregation (writes Agg split) -------------
#define EB 2048
__global__ void k_edges(const float* __restrict__ X)
{
    __shared__ unsigned int mwords[256];
    __shared__ int sc[256];
    __shared__ int lst[EB];
    __shared__ float cf[EB];
    __shared__ float abv[EB];
    __shared__ float s_rowsum;

    const int row = blockIdx.x;
    const int tid = threadIdx.x;

    unsigned int w0 = g_mask[row * 256 + tid];
    mwords[tid] = w0;
    int myp = __popc(w0);
    sc[tid] = myp;
    __syncthreads();
    for (int off = 1; off < 256; off <<= 1) {
        int v = (tid >= off) ? sc[tid - off] : 0;
        __syncthreads();
        sc[tid] += v;
        __syncthreads();
    }
    const int myoff = sc[tid] - myp;
    const int E = sc[255];
    if (tid == 0) s_rowsum = 0.0f;
    __syncthreads();

    float racc0 = 0.f, racc1 = 0.f, racc2 = 0.f;

    for (int start = 0; start < E; start += EB) {
        int end = (E < start + EB) ? E : (start + EB);
        int cnt = end - start;
        {
            unsigned int w = mwords[tid];
            int pos = myoff;
            while (w) {
                int b = __ffs(w) - 1;
                w &= w - 1;
                if (pos >= start && pos < end) lst[pos - start] = tid * 32 + b;
                pos++;
            }
        }
        __syncthreads();
        for (int e = tid; e < cnt; e += 256) {
            int j = lst[e];
            float ab = g_Ab[(size_t)row * Nn + j];
            abv[e] = ab;
            cf[e] = ab * g_G[j];
        }
        __syncthreads();
        if (tid == 0) {
            float s = s_rowsum;
            for (int e = 0; e < cnt; e++) s += abv[e];
            s_rowsum = s;
        }
        for (int e = 0; e < cnt; e++) {
            float c = cf[e];
            const float* xr = &X[(size_t)lst[e] * Dd];
            racc0 += c * xr[tid];
            racc1 += c * xr[tid + 256];
            racc2 += c * xr[tid + 512];
        }
        __syncthreads();
    }

    const size_t b = (size_t)row * Dd;
    float vs[3] = {racc0, racc1, racc2};
    #pragma unroll
    for (int s = 0; s < 3; s++) {
        bf16 h = __float2bfloat16_rn(vs[s]);
        g_Aggh[b + tid + s * 256] = h;
        g_Aggl[b + tid + s * 256] = __float2bfloat16_rn(vs[s] - __bfloat162float(h));
    }
    if (tid == 0) g_rowsum[row] = s_rowsum;
}

// ---------------- launch ----------------------------------------------------
extern "C" void kernel_launch(void* const* d_in, const int* in_sizes, int n_in,
                              void* d_out, int out_size)
{
    const float* X     = (const float*)d_in[0];
    const float* A     = (const float*)d_in[1];
    const float* W_gm  = (const float*)d_in[2];
    const float* ra    = (const float*)d_in[3];
    const float* gam   = (const float*)d_in[4];
    const float* ih_w1 = (const float*)d_in[5];
    const float* ih_b1 = (const float*)d_in[6];
    const float* ih_w2 = (const float*)d_in[7];
    const float* ih_b2 = (const float*)d_in[8];
    const float* ih_wh = (const float*)d_in[9];
    const float* ih_bh = (const float*)d_in[10];
    const float* gcn_w = (const float*)d_in[11];
    const float* gcn_b = (const float*)d_in[12];
    const float* fh_w1 = (const float*)d_in[13];
    const float* fh_b1 = (const float*)d_in[14];
    const float* fh_w2 = (const float*)d_in[15];
    const float* fh_b2 = (const float*)d_in[16];
    const float* fh_wh = (const float*)d_in[17];
    const float* fh_bh = (const float*)d_in[18];
    float* out = (float*)d_out;

    static float *pAb = nullptr, *pL2 = nullptr, *pRs = nullptr;
    static bf16 *pXh, *pXl, *pYh, *pYl, *pL1h, *pL1l, *pXph, *pXpl, *pAggh, *pAggl;
    static bf16 *pWgmTh, *pWgmTl, *pW1aTh, *pW1aTl, *pW2aTh, *pW2aTl;
    static bf16 *pGcnTh, *pGcnTl, *pW1bTh, *pW1bTl, *pW2bTh, *pW2bTl;
    if (!pAb) {
        cudaGetSymbolAddress((void**)&pAb, g_Ab);
        cudaGetSymbolAddress((void**)&pL2, g_L2);
        cudaGetSymbolAddress((void**)&pRs, g_rowsum);
        cudaGetSymbolAddress((void**)&pXh, g_Xh);   cudaGetSymbolAddress((void**)&pXl, g_Xl);
        cudaGetSymbolAddress((void**)&pYh, g_Yh);   cudaGetSymbolAddress((void**)&pYl, g_Yl);
        cudaGetSymbolAddress((void**)&pL1h, g_L1h); cudaGetSymbolAddress((void**)&pL1l, g_L1l);
        cudaGetSymbolAddress((void**)&pXph, g_Xph); cudaGetSymbolAddress((void**)&pXpl, g_Xpl);
        cudaGetSymbolAddress((void**)&pAggh, g_Aggh); cudaGetSymbolAddress((void**)&pAggl, g_Aggl);
        cudaGetSymbolAddress((void**)&pWgmTh, g_WgmTh); cudaGetSymbolAddress((void**)&pWgmTl, g_WgmTl);
        cudaGetSymbolAddress((void**)&pW1aTh, g_W1aTh); cudaGetSymbolAddress((void**)&pW1aTl, g_W1aTl);
        cudaGetSymbolAddress((void**)&pW2aTh, g_W2aTh); cudaGetSymbolAddress((void**)&pW2aTl, g_W2aTl);
        cudaGetSymbolAddress((void**)&pGcnTh, g_GcnTh); cudaGetSymbolAddress((void**)&pGcnTl, g_GcnTl);
        cudaGetSymbolAddress((void**)&pW1bTh, g_W1bTh); cudaGetSymbolAddress((void**)&pW1bTl, g_W1bTl);
        cudaGetSymbolAddress((void**)&pW2bTh, g_W2bTh); cudaGetSymbolAddress((void**)&pW2bTl, g_W2bTl);
        cudaFuncSetAttribute(k_hmma<0>, cudaFuncAttributeMaxDynamicSharedMemorySize, S_SMEM_BYTES);
        cudaFuncSetAttribute(k_hmma<1>, cudaFuncAttributeMaxDynamicSharedMemorySize, S_SMEM_BYTES);
        cudaFuncSetAttribute(k_hmma<2>, cudaFuncAttributeMaxDynamicSharedMemorySize, S_SMEM_BYTES);
        cudaFuncSetAttribute(k_hmma<3>, cudaFuncAttributeMaxDynamicSharedMemorySize, S_SMEM_BYTES);
        cudaFuncSetAttribute(k_hmma<4>, cudaFuncAttributeMaxDynamicSharedMemorySize, S_SMEM_BYTES);
    }

    dim3 blk(256);
    dim3 tsb(32, 8);

    // 0. splits and weight transposes (independent)
    k_split<<<2048, blk>>>(X, pXh, pXl, (size_t)Nn * Dd);
    k_tsplit<<<dim3(Dd / 32, Dd / 32), tsb>>>(W_gm, pWgmTh, pWgmTl, Dd, Dd);
    k_tsplit<<<dim3(H1s / 32, Dd / 32), tsb>>>(ih_w1, pW1aTh, pW1aTl, Dd, H1s);
    k_tsplit<<<dim3(H2s / 32, H1s / 32), tsb>>>(ih_w2, pW2aTh, pW2aTl, H1s, H2s);
    k_tsplit<<<dim3(Dd / 32, Dd / 32), tsb>>>(gcn_w, pGcnTh, pGcnTl, Dd, Dd);
    k_tsplit<<<dim3(H1s / 32, Dd / 32), tsb>>>(fh_w1, pW1bTh, pW1bTl, Dd, H1s);
    k_tsplit<<<dim3(H2s / 32, H1s / 32), tsb>>>(fh_w2, pW2bTh, pW2bTl, H1s, H2s);

    // 1. Y = X @ W_gm  -> split (EP4)
    k_hmma<4><<<dim3(Dd / 128, Nn / 128), blk, S_SMEM_BYTES>>>(
        pXh, pXl, pWgmTh, pWgmTl, nullptr, pYh, pYl, Dd, Dd,
        nullptr, nullptr, nullptr, nullptr, nullptr);

    // 2. Ab = al*A + (1-al)*relu(Y @ X^T)  (EP0)
    k_hmma<0><<<dim3(Nn / 128, Nn / 128), blk, S_SMEM_BYTES>>>(
        pYh, pYl, pXh, pXl, pAb, nullptr, nullptr, Nn, Dd,
        nullptr, nullptr, nullptr, A, ra);

    // 3. per-row top-5 + union mask
    k_topk2<<<Nn, blk>>>();
    k_zero_mask<<<2048, blk>>>();
    k_set_mask<<<(Nn * KK + 255) / 256, blk>>>();

    // 4. NIG head 1: L1 (EP1), L2 (EP2), head tail (computes G)
    k_hmma<1><<<dim3(H1s / 128, Nn / 128), blk, S_SMEM_BYTES>>>(
        pXh, pXl, pW1aTh, pW1aTl, nullptr, pL1h, pL1l, H1s, Dd,
        ih_b1, nullptr, nullptr, nullptr, nullptr);
    k_hmma<2><<<dim3(H2s / 128, Nn / 128), blk, S_SMEM_BYTES>>>(
        pL1h, pL1l, pW2aTh, pW2aTl, pL2, nullptr, nullptr, H2s, H1s,
        ih_b2, nullptr, nullptr, nullptr, nullptr);
    k_head_tail<<<Nn / 8, blk>>>(ih_wh, ih_bh, out, 1, gam);

    // 5. sparse aggregation -> Agg split + rowsum
    k_edges<<<Nn, blk>>>(X);

    // 6. Xp = X + gelu((Agg/rowsum) @ gcn_w + gcn_b)  (EP3 -> split)
    k_hmma<3><<<dim3(Dd / 128, Nn / 128), blk, S_SMEM_BYTES>>>(
        pAggh, pAggl, pGcnTh, pGcnTl, nullptr, pXph, pXpl, Dd, Dd,
        gcn_b, pRs, X, nullptr, nullptr);

    // 7. NIG head 2
    k_hmma<1><<<dim3(H1s / 128, Nn / 128), blk, S_SMEM_BYTES>>>(
        pXph, pXpl, pW1bTh, pW1bTl, nullptr, pL1h, pL1l, H1s, Dd,
        fh_b1, nullptr, nullptr, nullptr, nullptr);
    k_hmma<2><<<dim3(H2s / 128, Nn / 128), blk, S_SMEM_BYTES>>>(
        pL1h, pL1l, pW2bTh, pW2bTl, pL2, nullptr, nullptr, H2s, H1s,
        fh_b2, nullptr, nullptr, nullptr, nullptr);
    k_head_tail<<<Nn / 8, blk>>>(fh_wh, fh_bh, out + 4 * Nn, 0, nullptr);
}